// round 2
// baseline (speedup 1.0000x reference)
#include <cuda_runtime.h>
#include <math.h>

#define H 1024
#define S 65536
#define NBLK_SCORES 8192

// ---------------- scratch (no allocations allowed) ----------------
__device__ float  g_vpart[64 * H];        // 64 partial rows of v
__device__ float  g_v[H];                 // v = W^T @ hidden
__device__ float  g_scores[S];            // raw scores
__device__ float2 g_bpart[NBLK_SCORES];   // per-block (max, sumexp)
__device__ float2 g_MS;                   // global (max, sum)
__device__ unsigned int g_cnt_v = 0;      // ticket counters (self-resetting)
__device__ unsigned int g_cnt_s = 0;

// =====================================================================
// kernel 1: v = W^T @ hidden   (64 blocks compute partials; last block
// merges them — single launch instead of two)
// =====================================================================
__global__ void __launch_bounds__(256) k_v(const float* __restrict__ hidden,
                                           const float* __restrict__ W) {
    int t  = threadIdx.x;                  // 0..255, one float4 of j each
    int i0 = blockIdx.x * 16;
    float4 acc = make_float4(0.f, 0.f, 0.f, 0.f);
#pragma unroll
    for (int ii = 0; ii < 16; ii++) {
        float h = __ldg(&hidden[i0 + ii]);
        float4 w = reinterpret_cast<const float4*>(W + (size_t)(i0 + ii) * H)[t];
        acc.x += h * w.x; acc.y += h * w.y; acc.z += h * w.z; acc.w += h * w.w;
    }
    reinterpret_cast<float4*>(g_vpart + (size_t)blockIdx.x * H)[t] = acc;

    // ---- last-block merge ----
    __shared__ unsigned int s_ticket;
    __threadfence();
    if (t == 0) s_ticket = atomicAdd(&g_cnt_v, 1u);
    __syncthreads();
    if (s_ticket == 63u) {
        float4 sum = make_float4(0.f, 0.f, 0.f, 0.f);
#pragma unroll 8
        for (int p = 0; p < 64; p++) {
            float4 x = reinterpret_cast<const float4*>(g_vpart + (size_t)p * H)[t];
            sum.x += x.x; sum.y += x.y; sum.z += x.z; sum.w += x.w;
        }
        reinterpret_cast<float4*>(g_v)[t] = sum;
        if (t == 0) g_cnt_v = 0;           // reset for next graph replay
    }
}

// =====================================================================
// kernel 2: scores = enc @ v  + per-block (m,s) partials; the LAST
// block merges all 8192 partials into g_MS (no separate reduce kernel)
// =====================================================================
__global__ void __launch_bounds__(256) k_scores(const float* __restrict__ enc) {
    __shared__ float4 sv[256];
    __shared__ float  rowv[8];
    __shared__ float  sred[256];
    __shared__ unsigned int s_ticket;

    int t = threadIdx.x;
    sv[t] = reinterpret_cast<const float4*>(g_v)[t];
    __syncthreads();

    int warp = t >> 5, lane = t & 31;
    int row  = (blockIdx.x << 3) + warp;
    const float4* e = reinterpret_cast<const float4*>(enc + (size_t)row * H);

    float acc = 0.f;
#pragma unroll
    for (int k = 0; k < 8; k++) {
        float4 a = e[k * 32 + lane];
        float4 b = sv[k * 32 + lane];
        acc += a.x * b.x + a.y * b.y + a.z * b.z + a.w * b.w;
    }
#pragma unroll
    for (int o = 16; o; o >>= 1) acc += __shfl_xor_sync(0xffffffffu, acc, o);

    if (lane == 0) { g_scores[row] = acc; rowv[warp] = acc; }
    __syncthreads();

    if (t == 0) {
        float m = rowv[0];
#pragma unroll
        for (int i = 1; i < 8; i++) m = fmaxf(m, rowv[i]);
        float s = 0.f;
#pragma unroll
        for (int i = 0; i < 8; i++) s += __expf(rowv[i] - m);
        g_bpart[blockIdx.x] = make_float2(m, s);
    }

    // ---- last-block merge of all (m,s) partials ----
    __threadfence();
    if (t == 0) s_ticket = atomicAdd(&g_cnt_s, 1u);
    __syncthreads();
    if (s_ticket != NBLK_SCORES - 1u) return;

    // phase 1: global max (fmax only — no exp on the critical chain)
    float m_loc = -INFINITY;
#pragma unroll
    for (int k = 0; k < NBLK_SCORES / 256; k++)          // 32 per thread
        m_loc = fmaxf(m_loc, g_bpart[k * 256 + t].x);
    sred[t] = m_loc;
    __syncthreads();
#pragma unroll
    for (int off = 128; off; off >>= 1) {
        if (t < off) sred[t] = fmaxf(sred[t], sred[t + off]);
        __syncthreads();
    }
    float M = sred[0];
    __syncthreads();

    // phase 2: sum s_i * exp(m_i - M)  (independent exps, pipelined MUFU)
    float s_loc = 0.f;
#pragma unroll
    for (int k = 0; k < NBLK_SCORES / 256; k++) {
        float2 p = g_bpart[k * 256 + t];
        s_loc += p.y * __expf(p.x - M);
    }
    sred[t] = s_loc;
    __syncthreads();
#pragma unroll
    for (int off = 128; off; off >>= 1) {
        if (t < off) sred[t] += sred[t + off];
        __syncthreads();
    }
    if (t == 0) { g_MS = make_float2(M, sred[0]); g_cnt_s = 0; }
}

// =====================================================================
// kernel 3: normalize
// =====================================================================
__global__ void __launch_bounds__(256) k_norm(float* __restrict__ out) {
    int i = blockIdx.x * blockDim.x + threadIdx.x;   // 256 x 256 = 65536
    float2 ms = g_MS;
    float inv = 1.f / ms.y;
    out[i] = __expf(g_scores[i] - ms.x) * inv;
}

// ---------------- launch ----------------
extern "C" void kernel_launch(void* const* d_in, const int* in_sizes, int n_in,
                              void* d_out, int out_size) {
    const float* hidden = (const float*)d_in[0];   // [H]
    const float* enc    = (const float*)d_in[1];   // [S, H]
    const float* W      = (const float*)d_in[2];   // [H, H]
    // d_in[3] = b : dropped — softmax is shift-invariant to b.hidden
    float* out = (float*)d_out;                    // [S]

    k_v      <<<64,          256>>>(hidden, W);
    k_scores <<<NBLK_SCORES, 256>>>(enc);
    k_norm   <<<256,         256>>>(out);
}

// round 3
// speedup vs baseline: 1.0899x; 1.0899x over previous
#include <cuda_runtime.h>
#include <math.h>

#define H 1024
#define S 65536
#define NB_VPART 512           // 2 rows of W each
#define NB_SCORES 2048         // 32 rows of enc each

// ---------------- scratch (no allocations allowed) ----------------
__device__ float  g_vpart[NB_VPART * H]; // 512 partial v vectors (2 MB)
__device__ float  g_v[H];                // v = W^T @ hidden
__device__ float  g_scores[S];           // raw scores
__device__ float2 g_bpart[NB_SCORES];    // per-block (max, sumexp)
__device__ float2 g_MS;                  // global (max, sum)

// =====================================================================
// kernel 1: partial v. 512 blocks x 256 thr; block b sums rows {2b,2b+1}
// =====================================================================
__global__ void __launch_bounds__(256) k_vpart(const float* __restrict__ hidden,
                                               const float* __restrict__ W) {
    int t  = threadIdx.x;                 // float4 column
    int r0 = blockIdx.x * 2;
    float h0 = __ldg(&hidden[r0]);
    float h1 = __ldg(&hidden[r0 + 1]);
    float4 w0 = reinterpret_cast<const float4*>(W + (size_t)r0 * H)[t];
    float4 w1 = reinterpret_cast<const float4*>(W + (size_t)(r0 + 1) * H)[t];
    float4 acc;
    acc.x = h0 * w0.x + h1 * w1.x;
    acc.y = h0 * w0.y + h1 * w1.y;
    acc.z = h0 * w0.z + h1 * w1.z;
    acc.w = h0 * w0.w + h1 * w1.w;
    reinterpret_cast<float4*>(g_vpart + (size_t)blockIdx.x * H)[t] = acc;
}

// =====================================================================
// kernel 2: reduce 512 partials -> g_v. 16 blocks x 256 thr.
// thread = (pg, c): pg in [0,16), c in [0,16) float4-cols; sums 32 p's.
// =====================================================================
__global__ void __launch_bounds__(256) k_vreduce() {
    __shared__ float4 sm[256];
    int t  = threadIdx.x;
    int c  = t & 15;                      // float4 col within block
    int pg = t >> 4;                      // partial group
    int col = (blockIdx.x * 16 + c);      // global float4 col [0,256)

    float4 acc = make_float4(0.f, 0.f, 0.f, 0.f);
#pragma unroll 8
    for (int p = pg; p < NB_VPART; p += 16) {
        float4 x = reinterpret_cast<const float4*>(g_vpart)[(size_t)p * 256 + col];
        acc.x += x.x; acc.y += x.y; acc.z += x.z; acc.w += x.w;
    }
    sm[t] = acc;
    __syncthreads();
#pragma unroll
    for (int off = 128; off >= 16; off >>= 1) {
        if (t < off) {
            float4 a = sm[t], b = sm[t + off];
            a.x += b.x; a.y += b.y; a.z += b.z; a.w += b.w;
            sm[t] = a;
        }
        __syncthreads();
    }
    if (t < 16) reinterpret_cast<float4*>(g_v)[col] = sm[t];
}

// =====================================================================
// kernel 3: scores = enc @ v + per-block (m,s). 2048 blocks x 256 thr,
// 32 rows/block (each warp does 4 rows).
// =====================================================================
__global__ void __launch_bounds__(256) k_scores(const float* __restrict__ enc) {
    __shared__ float4 sv[256];
    __shared__ float  rowv[32];
    int t = threadIdx.x;
    sv[t] = reinterpret_cast<const float4*>(g_v)[t];
    __syncthreads();

    int warp = t >> 5, lane = t & 31;
#pragma unroll
    for (int r = 0; r < 4; r++) {
        int row = (blockIdx.x << 5) + (warp << 2) + r;
        const float4* e = reinterpret_cast<const float4*>(enc + (size_t)row * H);
        float acc = 0.f;
#pragma unroll
        for (int k = 0; k < 8; k++) {
            float4 a = e[k * 32 + lane];
            float4 b = sv[k * 32 + lane];
            acc += a.x * b.x + a.y * b.y + a.z * b.z + a.w * b.w;
        }
#pragma unroll
        for (int o = 16; o; o >>= 1) acc += __shfl_xor_sync(0xffffffffu, acc, o);
        if (lane == 0) { g_scores[row] = acc; rowv[(warp << 2) + r] = acc; }
    }
    __syncthreads();

    // warp 0: block (m,s) over 32 row scores, fully lane-parallel
    if (warp == 0) {
        float x = rowv[lane];
        float m = x;
#pragma unroll
        for (int o = 16; o; o >>= 1) m = fmaxf(m, __shfl_xor_sync(0xffffffffu, m, o));
        float p = __expf(x - m);
#pragma unroll
        for (int o = 16; o; o >>= 1) p += __shfl_xor_sync(0xffffffffu, p, o);
        if (lane == 0) g_bpart[blockIdx.x] = make_float2(m, p);
    }
}

// =====================================================================
// kernel 4: merge 2048 (m,s) partials. 1 block x 1024 thr, two phases.
// =====================================================================
__global__ void __launch_bounds__(1024) k_msreduce() {
    __shared__ float sred[1024];
    int t = threadIdx.x;

    float2 a = g_bpart[t];
    float2 b = g_bpart[t + 1024];
    float m_loc = fmaxf(a.x, b.x);
    sred[t] = m_loc;
    __syncthreads();
#pragma unroll
    for (int off = 512; off; off >>= 1) {
        if (t < off) sred[t] = fmaxf(sred[t], sred[t + off]);
        __syncthreads();
    }
    float M = sred[0];
    __syncthreads();

    float s_loc = a.y * __expf(a.x - M) + b.y * __expf(b.x - M);
    sred[t] = s_loc;
    __syncthreads();
#pragma unroll
    for (int off = 512; off; off >>= 1) {
        if (t < off) sred[t] += sred[t + off];
        __syncthreads();
    }
    if (t == 0) g_MS = make_float2(M, sred[0]);
}

// =====================================================================
// kernel 5: normalize (float4)
// =====================================================================
__global__ void __launch_bounds__(256) k_norm(float* __restrict__ out) {
    int i = blockIdx.x * blockDim.x + threadIdx.x;   // 64 x 256 float4 = 65536
    float2 ms = g_MS;
    float inv = 1.f / ms.y;
    float4 s = reinterpret_cast<const float4*>(g_scores)[i];
    float4 o;
    o.x = __expf(s.x - ms.x) * inv;
    o.y = __expf(s.y - ms.x) * inv;
    o.z = __expf(s.z - ms.x) * inv;
    o.w = __expf(s.w - ms.x) * inv;
    reinterpret_cast<float4*>(out)[i] = o;
}

// ---------------- launch ----------------
extern "C" void kernel_launch(void* const* d_in, const int* in_sizes, int n_in,
                              void* d_out, int out_size) {
    const float* hidden = (const float*)d_in[0];   // [H]
    const float* enc    = (const float*)d_in[1];   // [S, H]
    const float* W      = (const float*)d_in[2];   // [H, H]
    // d_in[3] = b : dropped — softmax is shift-invariant to b.hidden
    float* out = (float*)d_out;                    // [S]

    k_vpart   <<<NB_VPART,  256>>>(hidden, W);
    k_vreduce <<<16,        256>>>();
    k_scores  <<<NB_SCORES, 256>>>(enc);
    k_msreduce<<<1,        1024>>>();
    k_norm    <<<64,        256>>>(out);
}

// round 4
// speedup vs baseline: 1.2139x; 1.1137x over previous
#include <cuda_runtime.h>
#include <math.h>

#define H 1024
#define S 65536
#define NB_VPART 512            // 2 rows of W each
#define NB_SCORES 4096          // 16 rows of enc each
#define NB_NORM 64

// ---------------- scratch (no allocations allowed) ----------------
__device__ float  g_vpart[NB_VPART * H]; // 512 partial v vectors (2 MB)
__device__ float  g_v[H];                // v = W^T @ hidden
__device__ float  g_scores[S];           // raw scores
__device__ float2 g_bpart[NB_SCORES];    // per-block (max, sumexp)

// =====================================================================
// kernel 1: partial v. 512 blocks x 256 thr; block b sums rows {2b,2b+1}
// =====================================================================
__global__ void __launch_bounds__(256) k_vpart(const float* __restrict__ hidden,
                                               const float* __restrict__ W) {
    int t  = threadIdx.x;                 // float4 column
    int r0 = blockIdx.x * 2;
    float h0 = __ldg(&hidden[r0]);
    float h1 = __ldg(&hidden[r0 + 1]);
    float4 w0 = reinterpret_cast<const float4*>(W + (size_t)r0 * H)[t];
    float4 w1 = reinterpret_cast<const float4*>(W + (size_t)(r0 + 1) * H)[t];
    float4 acc;
    acc.x = h0 * w0.x + h1 * w1.x;
    acc.y = h0 * w0.y + h1 * w1.y;
    acc.z = h0 * w0.z + h1 * w1.z;
    acc.w = h0 * w0.w + h1 * w1.w;
    reinterpret_cast<float4*>(g_vpart + (size_t)blockIdx.x * H)[t] = acc;
}

// =====================================================================
// kernel 2: reduce 512 partials -> g_v. 16 blocks x 256 thr.
// =====================================================================
__global__ void __launch_bounds__(256) k_vreduce() {
    __shared__ float4 sm[256];
    int t  = threadIdx.x;
    int c  = t & 15;                      // float4 col within block
    int pg = t >> 4;                      // partial group
    int col = (blockIdx.x * 16 + c);      // global float4 col [0,256)

    float4 acc = make_float4(0.f, 0.f, 0.f, 0.f);
#pragma unroll 8
    for (int p = pg; p < NB_VPART; p += 16) {
        float4 x = reinterpret_cast<const float4*>(g_vpart)[(size_t)p * 256 + col];
        acc.x += x.x; acc.y += x.y; acc.z += x.z; acc.w += x.w;
    }
    sm[t] = acc;
    __syncthreads();
#pragma unroll
    for (int off = 128; off >= 16; off >>= 1) {
        if (t < off) {
            float4 a = sm[t], b = sm[t + off];
            a.x += b.x; a.y += b.y; a.z += b.z; a.w += b.w;
            sm[t] = a;
        }
        __syncthreads();
    }
    if (t < 16) reinterpret_cast<float4*>(g_v)[col] = sm[t];
}

// =====================================================================
// kernel 3: scores = enc @ v + per-block (m,s). 4096 blocks x 256 thr,
// 16 rows/block (each warp does 2 rows).
// =====================================================================
__global__ void __launch_bounds__(256) k_scores(const float* __restrict__ enc) {
    __shared__ float4 sv[256];
    __shared__ float  rowv[16];
    int t = threadIdx.x;
    sv[t] = reinterpret_cast<const float4*>(g_v)[t];
    __syncthreads();

    int warp = t >> 5, lane = t & 31;
#pragma unroll
    for (int r = 0; r < 2; r++) {
        int row = (blockIdx.x << 4) + (warp << 1) + r;
        const float4* e = reinterpret_cast<const float4*>(enc + (size_t)row * H);
        float acc = 0.f;
#pragma unroll
        for (int k = 0; k < 8; k++) {
            float4 a = e[k * 32 + lane];
            float4 b = sv[k * 32 + lane];
            acc += a.x * b.x + a.y * b.y + a.z * b.z + a.w * b.w;
        }
#pragma unroll
        for (int o = 16; o; o >>= 1) acc += __shfl_xor_sync(0xffffffffu, acc, o);
        if (lane == 0) { g_scores[row] = acc; rowv[(warp << 1) + r] = acc; }
    }
    __syncthreads();

    // warp 0: block (m,s) over 16 row scores, lane-parallel
    if (warp == 0) {
        float x = (lane < 16) ? rowv[lane] : -INFINITY;
        float m = x;
#pragma unroll
        for (int o = 16; o; o >>= 1) m = fmaxf(m, __shfl_xor_sync(0xffffffffu, m, o));
        float p = (lane < 16) ? __expf(x - m) : 0.f;
#pragma unroll
        for (int o = 16; o; o >>= 1) p += __shfl_xor_sync(0xffffffffu, p, o);
        if (lane == 0) g_bpart[blockIdx.x] = make_float2(m, p);
    }
}

// =====================================================================
// kernel 4: normalize. Each of 64 blocks REDUNDANTLY merges all 4096
// (m,s) partials (deterministic, L2-resident), then normalizes its
// 1024-element slice. No single-block merge kernel needed.
// =====================================================================
__global__ void __launch_bounds__(256) k_norm(float* __restrict__ out) {
    __shared__ float sred[256];
    int t = threadIdx.x;

    // load 16 partials per thread into registers (one pass over g_bpart)
    float2 p[16];
#pragma unroll
    for (int k = 0; k < 16; k++) p[k] = g_bpart[k * 256 + t];

    // phase 1: global max
    float m_loc = p[0].x;
#pragma unroll
    for (int k = 1; k < 16; k++) m_loc = fmaxf(m_loc, p[k].x);
    sred[t] = m_loc;
    __syncthreads();
#pragma unroll
    for (int off = 128; off; off >>= 1) {
        if (t < off) sred[t] = fmaxf(sred[t], sred[t + off]);
        __syncthreads();
    }
    float M = sred[0];
    __syncthreads();

    // phase 2: sum s_i * exp(m_i - M)  (independent MUFU exps)
    float s_loc = 0.f;
#pragma unroll
    for (int k = 0; k < 16; k++) s_loc += p[k].y * __expf(p[k].x - M);
    sred[t] = s_loc;
    __syncthreads();
#pragma unroll
    for (int off = 128; off; off >>= 1) {
        if (t < off) sred[t] += sred[t + off];
        __syncthreads();
    }
    float inv = 1.f / sred[0];

    // normalize this block's 1024-element slice (256 float4s)
    int i = blockIdx.x * 256 + t;
    float4 s = reinterpret_cast<const float4*>(g_scores)[i];
    float4 o;
    o.x = __expf(s.x - M) * inv;
    o.y = __expf(s.y - M) * inv;
    o.z = __expf(s.z - M) * inv;
    o.w = __expf(s.w - M) * inv;
    reinterpret_cast<float4*>(out)[i] = o;
}

// ---------------- launch ----------------
extern "C" void kernel_launch(void* const* d_in, const int* in_sizes, int n_in,
                              void* d_out, int out_size) {
    const float* hidden = (const float*)d_in[0];   // [H]
    const float* enc    = (const float*)d_in[1];   // [S, H]
    const float* W      = (const float*)d_in[2];   // [H, H]
    // d_in[3] = b : dropped — softmax is shift-invariant to b.hidden
    float* out = (float*)d_out;                    // [S]

    k_vpart   <<<NB_VPART,  256>>>(hidden, W);
    k_vreduce <<<16,        256>>>();
    k_scores  <<<NB_SCORES, 256>>>(enc);
    k_norm    <<<NB_NORM,   256>>>(out);
}

// round 5
// speedup vs baseline: 1.2299x; 1.0132x over previous
#include <cuda_runtime.h>
#include <math.h>

#define H 1024
#define S 65536
#define NB_VPART 512            // 2 rows of W each
#define NB_SCORES 4096          // 16 rows of enc each
#define NB_NORM 64

// ---------------- scratch (no allocations allowed) ----------------
__device__ float    g_vpart[NB_VPART * H]; // 512 partial v vectors (2 MB)
__device__ float    g_v[H];                // v = W^T @ hidden
__device__ float    g_scores[S];           // raw scores
__device__ float2   g_bpart[NB_SCORES];    // per-block (max, sumexp)
__device__ unsigned g_Mu;                  // global max, order-encoded uint

// ordered-uint encoding of float (monotonic): deterministic atomicMax
__device__ __forceinline__ unsigned encf(float f) {
    unsigned b = __float_as_uint(f);
    return (b & 0x80000000u) ? ~b : (b | 0x80000000u);
}
__device__ __forceinline__ float decf(unsigned u) {
    unsigned b = (u & 0x80000000u) ? (u & 0x7fffffffu) : ~u;
    return __uint_as_float(b);
}

// =====================================================================
// kernel 1: partial v. 512 blocks x 256 thr; block b sums rows {2b,2b+1}
// Also resets g_Mu for this graph replay (consumed 2 kernels later).
// =====================================================================
__global__ void __launch_bounds__(256) k_vpart(const float* __restrict__ hidden,
                                               const float* __restrict__ W) {
    int t  = threadIdx.x;                 // float4 column
    if (blockIdx.x == 0 && t == 0) g_Mu = 0u;   // enc(-inf) lower bound
    int r0 = blockIdx.x * 2;
    float h0 = __ldg(&hidden[r0]);
    float h1 = __ldg(&hidden[r0 + 1]);
    float4 w0 = reinterpret_cast<const float4*>(W + (size_t)r0 * H)[t];
    float4 w1 = reinterpret_cast<const float4*>(W + (size_t)(r0 + 1) * H)[t];
    float4 acc;
    acc.x = h0 * w0.x + h1 * w1.x;
    acc.y = h0 * w0.y + h1 * w1.y;
    acc.z = h0 * w0.z + h1 * w1.z;
    acc.w = h0 * w0.w + h1 * w1.w;
    reinterpret_cast<float4*>(g_vpart + (size_t)blockIdx.x * H)[t] = acc;
}

// =====================================================================
// kernel 2: reduce 512 partials -> g_v. 16 blocks x 256 thr.  (PDL)
// =====================================================================
__global__ void __launch_bounds__(256) k_vreduce() {
#if __CUDA_ARCH__ >= 900
    cudaGridDependencySynchronize();
#endif
    __shared__ float4 sm[256];
    int t  = threadIdx.x;
    int c  = t & 15;                      // float4 col within block
    int pg = t >> 4;                      // partial group
    int col = (blockIdx.x * 16 + c);      // global float4 col [0,256)

    float4 acc = make_float4(0.f, 0.f, 0.f, 0.f);
#pragma unroll 8
    for (int p = pg; p < NB_VPART; p += 16) {
        float4 x = reinterpret_cast<const float4*>(g_vpart)[(size_t)p * 256 + col];
        acc.x += x.x; acc.y += x.y; acc.z += x.z; acc.w += x.w;
    }
    sm[t] = acc;
    __syncthreads();
#pragma unroll
    for (int off = 128; off >= 16; off >>= 1) {
        if (t < off) {
            float4 a = sm[t], b = sm[t + off];
            a.x += b.x; a.y += b.y; a.z += b.z; a.w += b.w;
            sm[t] = a;
        }
        __syncthreads();
    }
    if (t < 16) reinterpret_cast<float4*>(g_v)[col] = sm[t];
}

// =====================================================================
// kernel 3: scores = enc @ v + per-block (m,s) + atomicMax global M.
// 4096 blocks x 256 thr, 16 rows/block (each warp does 2 rows). (PDL)
// =====================================================================
__global__ void __launch_bounds__(256) k_scores(const float* __restrict__ enc) {
    __shared__ float4 sv[256];
    __shared__ float  rowv[16];
    int t = threadIdx.x;
    int warp = t >> 5, lane = t & 31;
#if __CUDA_ARCH__ >= 900
    cudaGridDependencySynchronize();
#endif
    sv[t] = reinterpret_cast<const float4*>(g_v)[t];
    __syncthreads();

#pragma unroll
    for (int r = 0; r < 2; r++) {
        int row = (blockIdx.x << 4) + (warp << 1) + r;
        const float4* e = reinterpret_cast<const float4*>(enc + (size_t)row * H);
        float acc = 0.f;
#pragma unroll
        for (int k = 0; k < 8; k++) {
            float4 a = e[k * 32 + lane];
            float4 b = sv[k * 32 + lane];
            acc += a.x * b.x + a.y * b.y + a.z * b.z + a.w * b.w;
        }
#pragma unroll
        for (int o = 16; o; o >>= 1) acc += __shfl_xor_sync(0xffffffffu, acc, o);
        if (lane == 0) { g_scores[row] = acc; rowv[(warp << 1) + r] = acc; }
    }
    __syncthreads();

    // warp 0: block (m,s) over 16 row scores, lane-parallel
    if (warp == 0) {
        float x = (lane < 16) ? rowv[lane] : -INFINITY;
        float m = x;
#pragma unroll
        for (int o = 16; o; o >>= 1) m = fmaxf(m, __shfl_xor_sync(0xffffffffu, m, o));
        float p = (lane < 16) ? __expf(x - m) : 0.f;
#pragma unroll
        for (int o = 16; o; o >>= 1) p += __shfl_xor_sync(0xffffffffu, p, o);
        if (lane == 0) {
            g_bpart[blockIdx.x] = make_float2(m, p);
            atomicMax(&g_Mu, encf(m));    // order-independent => deterministic
        }
    }
}

// =====================================================================
// kernel 4: normalize. M comes from g_Mu; each block redundantly sums
// s_i*exp(m_i-M) with shfl reductions (2 barriers), then normalizes
// its 1024-element slice.  (PDL)
// =====================================================================
__global__ void __launch_bounds__(256) k_norm(float* __restrict__ out) {
    __shared__ float swarp[8];
    __shared__ float sS;
    int t = threadIdx.x;
    int warp = t >> 5, lane = t & 31;
#if __CUDA_ARCH__ >= 900
    cudaGridDependencySynchronize();
#endif
    float M = decf(g_Mu);

    // sum phase: 16 partials per thread, independent MUFU exps
    float s_loc = 0.f;
#pragma unroll
    for (int k = 0; k < 16; k++) {
        float2 p = g_bpart[k * 256 + t];
        s_loc += p.y * __expf(p.x - M);
    }
#pragma unroll
    for (int o = 16; o; o >>= 1) s_loc += __shfl_xor_sync(0xffffffffu, s_loc, o);
    if (lane == 0) swarp[warp] = s_loc;
    __syncthreads();
    if (warp == 0) {
        float v = (lane < 8) ? swarp[lane] : 0.f;
#pragma unroll
        for (int o = 4; o; o >>= 1) v += __shfl_xor_sync(0xffffffffu, v, o);
        if (lane == 0) sS = v;
    }
    __syncthreads();
    float inv = 1.f / sS;

    // normalize this block's 1024-element slice (256 float4s)
    int i = blockIdx.x * 256 + t;
    float4 s = reinterpret_cast<const float4*>(g_scores)[i];
    float4 o;
    o.x = __expf(s.x - M) * inv;
    o.y = __expf(s.y - M) * inv;
    o.z = __expf(s.z - M) * inv;
    o.w = __expf(s.w - M) * inv;
    reinterpret_cast<float4*>(out)[i] = o;
}

// ---------------- launch (PDL on dependent edges) ----------------
static void launch_pdl(void* fn, dim3 grid, dim3 block, void** args) {
    cudaLaunchConfig_t cfg = {};
    cfg.gridDim = grid;
    cfg.blockDim = block;
    cfg.dynamicSmemBytes = 0;
    cfg.stream = 0;
    cudaLaunchAttribute attr[1];
    attr[0].id = cudaLaunchAttributeProgrammaticStreamSerialization;
    attr[0].val.programmaticStreamSerializationAllowed = 1;
    cfg.attrs = attr;
    cfg.numAttrs = 1;
    cudaLaunchKernelExC(&cfg, fn, args);
}

extern "C" void kernel_launch(void* const* d_in, const int* in_sizes, int n_in,
                              void* d_out, int out_size) {
    const float* hidden = (const float*)d_in[0];   // [H]
    const float* enc    = (const float*)d_in[1];   // [S, H]
    const float* W      = (const float*)d_in[2];   // [H, H]
    // d_in[3] = b : dropped — softmax is shift-invariant to b.hidden
    float* out = (float*)d_out;                    // [S]

    k_vpart<<<NB_VPART, 256>>>(hidden, W);

    void* a1[] = {};
    launch_pdl((void*)k_vreduce, dim3(16), dim3(256), a1);

    void* a2[] = {(void*)&enc};
    launch_pdl((void*)k_scores, dim3(NB_SCORES), dim3(256), a2);

    void* a3[] = {(void*)&out};
    launch_pdl((void*)k_norm, dim3(NB_NORM), dim3(256), a3);
}